// round 13
// baseline (speedup 1.0000x reference)
#include <cuda_runtime.h>
#include <cuda_fp16.h>
#include <cstdint>

// ---------------------------------------------------------------------------
// GeneralizedRCNNExtractModel via HMMA (mma.sync f16) GEMMs.
//   f6     = relu(x @ W6 + b6)            2000x12544 @ 12544x1024
//   f7     = relu(f6 @ W7 + b7)           2000x1024  @ 1024x1024
//   logits = f7 @ [Wcls|Wbox] + bias      2000x1024 @ 1024x405 (pad 512)
// R13: single-pass fp16 GEMMs with K-chunk 64 (was 32): halves barrier +
// cp.async issue events per MMA and doubles the MMA run length between
// syncs — R12 showed 1-pass exposes per-chunk overhead (tensor 39.7%).
// Tiles use native 128B-row SW128 swizzle.
// ---------------------------------------------------------------------------

#define NUM_CLASSES 81
#define SCORE_THRESH 0.05f
#define BBOX_XFORM_CLIP 4.135166556742356f

#define RMAX 2000
#define KDIM 12544
#define HDIM 1024
#define NHEAD 512   // 405 used, padded

// --------------------------- device scratch -------------------------------
__device__ __half g_xh[RMAX * KDIM];     // fp16 x
__device__ __half g_w6h[HDIM * KDIM];    // W6^T fp16 [N][K]
__device__ __half g_w7h[HDIM * HDIM];    // W7^T fp16
__device__ __half g_whh[NHEAD * HDIM];   // [Wcls|Wbox]^T; rows 405..511 zero
__device__ __half g_f6h[RMAX * HDIM];
__device__ __half g_f7h[RMAX * HDIM];
__device__ float  g_part[2 * RMAX * HDIM];   // split-K partials

// --------------------------- PTX helpers ----------------------------------
__device__ __forceinline__ uint32_t smem_to_u32(const void* p) {
    uint32_t a;
    asm("{ .reg .u64 t; cvta.to.shared.u64 t, %1; cvt.u32.u64 %0, t; }"
        : "=r"(a) : "l"(p));
    return a;
}
__device__ __forceinline__ void cp_async16(uint32_t dst, const void* src, bool pred) {
    int sz = pred ? 16 : 0;
    asm volatile("cp.async.cg.shared.global [%0], [%1], 16, %2;"
                 :: "r"(dst), "l"(src), "r"(sz) : "memory");
}
#define CP_COMMIT() asm volatile("cp.async.commit_group;" ::: "memory")
#define CP_WAIT(N)  asm volatile("cp.async.wait_group %0;" :: "n"(N) : "memory")

__device__ __forceinline__ void ldsm_x4(uint32_t& r0, uint32_t& r1,
                                        uint32_t& r2, uint32_t& r3, uint32_t addr) {
    asm volatile("ldmatrix.sync.aligned.m8n8.x4.shared.b16 {%0,%1,%2,%3}, [%4];"
                 : "=r"(r0), "=r"(r1), "=r"(r2), "=r"(r3) : "r"(addr));
}
__device__ __forceinline__ void mma16816h(float* c, const uint32_t* a,
                                          uint32_t b0, uint32_t b1) {
    asm volatile(
        "mma.sync.aligned.m16n8k16.row.col.f32.f16.f16.f32 "
        "{%0,%1,%2,%3}, {%4,%5,%6,%7}, {%8,%9}, {%0,%1,%2,%3};"
        : "+f"(c[0]), "+f"(c[1]), "+f"(c[2]), "+f"(c[3])
        : "r"(a[0]), "r"(a[1]), "r"(a[2]), "r"(a[3]), "r"(b0), "r"(b1));
}

// SW128 swizzle for 128B rows: chunk c (16B units, 0..7) xor row&7.
__device__ __forceinline__ uint32_t sw128(int row, int chunk) {
    return (uint32_t)(row * 128 + ((chunk ^ (row & 7)) << 4));
}
// 64B-row swizzle (prep transposes only)
__device__ __forceinline__ uint32_t swoff(int row, int chunk) {
    return (uint32_t)(row * 64 + ((chunk ^ ((row >> 1) & 3)) << 4));
}

// --------------------------- mega prep kernel -----------------------------
#define NBX 1024

__device__ void transpose_half_job(const float* __restrict__ W, int K, int Nsrc,
                                   int ldT, int rowoff,
                                   __half* __restrict__ Th, int lb, int tid) {
    __shared__ float t[32][33];
    const int ntn = (Nsrc + 31) / 32;
    const int n0 = (lb % ntn) * 32;
    const int k0 = (lb / ntn) * 32;
    const int tx = tid & 31, ty = tid >> 5;  // 32 x 8
#pragma unroll
    for (int i = 0; i < 32; i += 8) {
        float v = 0.f;
        if (n0 + tx < Nsrc)
            v = W[(size_t)(k0 + ty + i) * Nsrc + n0 + tx];
        t[ty + i][tx] = v;
    }
    __syncthreads();
#pragma unroll
    for (int i = 0; i < 32; i += 8) {
        const int n = n0 + ty + i;
        if (n >= Nsrc) continue;
        Th[(size_t)(rowoff + n) * ldT + k0 + tx] = __float2half(t[tx][ty + i]);
    }
}

__global__ __launch_bounds__(256)
void prep_kernel(const float* __restrict__ x,
                 const float* __restrict__ W6,
                 const float* __restrict__ W7,
                 const float* __restrict__ Wcls,
                 const float* __restrict__ Wbox,
                 __half* __restrict__ xh,
                 __half* __restrict__ w6h,
                 __half* __restrict__ w7h,
                 __half* __restrict__ whh,
                 int M, int K1, int H, int NC) {
    const int tid = threadIdx.x;
    const int nbW6 = (H / 32) * (K1 / 32);
    const int nbW7 = (H / 32) * (H / 32);
    const int nbWc = ((NC + 31) / 32) * (H / 32);
    const int nbWb = ((NC * 4 + 31) / 32) * (H / 32);
    int b = blockIdx.x;

    if (b < NBX) {
        const size_t n4 = ((size_t)M * K1) / 4;
        size_t i = (size_t)b * 256 + tid;
        const size_t stride = (size_t)NBX * 256;
        const float4* X4 = reinterpret_cast<const float4*>(x);
        __half2* H2 = reinterpret_cast<__half2*>(xh);
        for (; i < n4; i += stride) {
            float4 v = X4[i];
            H2[i * 2 + 0] = __half2(__float2half(v.x), __float2half(v.y));
            H2[i * 2 + 1] = __half2(__float2half(v.z), __float2half(v.w));
        }
        return;
    }
    b -= NBX;
    if (b < nbW6) { transpose_half_job(W6, K1, H, K1, 0, w6h, b, tid); return; }
    b -= nbW6;
    if (b < nbW7) { transpose_half_job(W7, H, H, H, 0, w7h, b, tid); return; }
    b -= nbW7;
    if (b < nbWc) { transpose_half_job(Wcls, H, NC, H, 0, whh, b, tid); return; }
    b -= nbWc;
    if (b < nbWb) { transpose_half_job(Wbox, H, NC * 4, H, NC, whh, b, tid); return; }
}

// --------------------------- fp16 1-pass GEMM (split-K, chunk 64) ---------
// Partial[z][M][N] = sum over K-slice z of A@B^T (pure fp16, f32 accum).
// Block 128x128, 4 warps of 64x64. Stage = A 16K | B 16K (32KB), 3-stage
// cp.async pipeline (96KB smem), 2 CTAs/SM. Ksl%64==0, N%128==0.
__global__ __launch_bounds__(128, 2)
void hmma_gemm_f16(int M, int N, int K, int Ksl,
                   const __half* __restrict__ A,
                   const __half* __restrict__ B,
                   float* __restrict__ Pout) {
    extern __shared__ char smem[];
    const uint32_t sbase = smem_to_u32(smem);
    const int tid = threadIdx.x, lane = tid & 31, wid = tid >> 5;
    const int bm = blockIdx.y * 128, bn = blockIdx.x * 128;
    const int wm = (wid & 1) * 64, wn = (wid >> 1) * 64;
    const int kbase = blockIdx.z * Ksl;

    constexpr uint32_t STAGE = 32768u;   // A 16K | B 16K
    constexpr int NSTAGE = 3;

    // ---- cp.async per-thread addressing: 128x64 fp16 tile = 1024 x 16B ----
    uint32_t offT[8];
    size_t gofA[8], gofB[8];
    bool predA[8];
#pragma unroll
    for (int i = 0; i < 8; ++i) {
        const int idx = tid + i * 128;            // 0..1023
        const int row = idx >> 3, ch = idx & 7;   // 128 rows x 8 chunks(16B)
        offT[i] = sw128(row, ch);
        const int ra = (bm + row < M) ? (bm + row) : (M - 1);
        predA[i] = (bm + row < M);
        gofA[i] = (size_t)ra * K + kbase + ch * 8;
        gofB[i] = (size_t)(bn + row) * K + kbase + ch * 8;
    }

    // ---- ldmatrix fragment addressing (row base + per-kc chunk xor) ----
    uint32_t aRB[4], bRB[4];
    int aRM[4], bRM[4];
    const int aC0 = lane >> 4;                 // 0..1
    const int bC0 = (lane >> 3) & 1;           // 0..1
#pragma unroll
    for (int mt = 0; mt < 4; ++mt) {
        const int row = wm + mt * 16 + (lane & 15);
        aRB[mt] = (uint32_t)(row * 128);
        aRM[mt] = row & 7;
    }
#pragma unroll
    for (int nt = 0; nt < 4; ++nt) {
        const int row = wn + nt * 16 + ((lane & 7) | ((lane >> 4) << 3));
        bRB[nt] = (uint32_t)(row * 128);
        bRM[nt] = row & 7;
    }

    float acc[4][8][4];
#pragma unroll
    for (int mt = 0; mt < 4; ++mt)
#pragma unroll
        for (int nf = 0; nf < 8; ++nf)
#pragma unroll
            for (int k = 0; k < 4; ++k) acc[mt][nf][k] = 0.f;

    const int S = Ksl / 64;

    auto issue = [&](int step) {
        const size_t k0 = (size_t)step * 64;
        const uint32_t st = (uint32_t)(step % NSTAGE) * STAGE;
#pragma unroll
        for (int i = 0; i < 8; ++i) {
            cp_async16(sbase + st + offT[i],          A + gofA[i] + k0, predA[i]);
            cp_async16(sbase + st + 16384 + offT[i],  B + gofB[i] + k0, true);
        }
        CP_COMMIT();
    };

    issue(0);
    if (S > 1) issue(1);

#pragma unroll 1
    for (int s = 0; s < S; ++s) {
        if (s + 1 < S) { CP_WAIT(1); } else { CP_WAIT(0); }
        __syncthreads();
        if (s + 2 < S) issue(s + 2);

        const uint32_t baseA = sbase + (uint32_t)(s % NSTAGE) * STAGE;
        const uint32_t baseB = baseA + 16384u;
#pragma unroll
        for (int kc = 0; kc < 4; ++kc) {
            uint32_t a[4][4];
#pragma unroll
            for (int mt = 0; mt < 4; ++mt) {
                const uint32_t ad = baseA + aRB[mt] +
                    (uint32_t)((((aC0 + kc * 2) ^ aRM[mt])) << 4);
                ldsm_x4(a[mt][0], a[mt][1], a[mt][2], a[mt][3], ad);
            }
#pragma unroll
            for (int nt = 0; nt < 4; ++nt) {
                const uint32_t bd = baseB + bRB[nt] +
                    (uint32_t)((((bC0 + kc * 2) ^ bRM[nt])) << 4);
                uint32_t b0, b1, b2, b3;
                ldsm_x4(b0, b1, b2, b3, bd);
#pragma unroll
                for (int mt = 0; mt < 4; ++mt) {
                    mma16816h(acc[mt][nt * 2 + 0], a[mt], b0, b1);
                    mma16816h(acc[mt][nt * 2 + 1], a[mt], b2, b3);
                }
            }
        }
    }

    float* P = Pout + (size_t)blockIdx.z * M * N;
#pragma unroll
    for (int mt = 0; mt < 4; ++mt) {
#pragma unroll
        for (int nf = 0; nf < 8; ++nf) {
            const int col = bn + wn + nf * 8 + (lane & 3) * 2;
#pragma unroll
            for (int half = 0; half < 2; ++half) {
                const int row = bm + wm + mt * 16 + (lane >> 2) + half * 8;
                if (row >= M) continue;
                *reinterpret_cast<float2*>(&P[(size_t)row * N + col]) =
                    make_float2(acc[mt][nf][half * 2 + 0],
                                acc[mt][nf][half * 2 + 1]);
            }
        }
    }
}

// --------------------------- split-K reduce + epilogue --------------------
__global__ __launch_bounds__(256)
void reduce_epilogue(int M, int N,
                     const float* __restrict__ P,
                     const float* __restrict__ bias, int do_relu,
                     float* __restrict__ C, int ldc,
                     __half* __restrict__ Oh, int ldo) {
    const size_t i = (size_t)blockIdx.x * blockDim.x + threadIdx.x;
    const size_t n2 = (size_t)M * N / 2;
    if (i >= n2) return;
    const float2 p0 = reinterpret_cast<const float2*>(P)[i];
    const float2 p1 = reinterpret_cast<const float2*>(P + (size_t)M * N)[i];
    const int col = (int)((i * 2) % N);
    const int row = (int)((i * 2) / N);
    float v0 = p0.x + p1.x + bias[col];
    float v1 = p0.y + p1.y + bias[col + 1];
    if (do_relu) { v0 = fmaxf(v0, 0.f); v1 = fmaxf(v1, 0.f); }
    if (C)
        *reinterpret_cast<float2*>(&C[(size_t)row * ldc + col]) =
            make_float2(v0, v1);
    if (Oh)
        *reinterpret_cast<__half2*>(&Oh[(size_t)row * ldo + col]) =
            __half2(__float2half(v0), __float2half(v1));
}

// --------------------------- postprocess (+head reduce) -------------------
__global__ __launch_bounds__(128)
void postprocess_kernel(int M,
                        const float* __restrict__ P,   // [2][M][NHEAD]
                        const float* __restrict__ bcls,
                        const float* __restrict__ bbox_b,
                        const float* __restrict__ boxes,
                        float* __restrict__ out, int ldo) {
    const int r = blockIdx.x;
    const int t = threadIdx.x;
    __shared__ float sl[NUM_CLASSES * 5];  // 405
    __shared__ float smax, ssum;

    const float* p0 = P + (size_t)r * NHEAD;
    const float* p1 = P + (size_t)M * NHEAD + (size_t)r * NHEAD;
    for (int i = t; i < NUM_CLASSES * 5; i += 128) {
        const float bias = (i < NUM_CLASSES) ? bcls[i] : bbox_b[i - NUM_CLASSES];
        sl[i] = p0[i] + p1[i] + bias;
    }
    __syncthreads();

    if (t == 0) {
        float m = -1e30f;
        for (int i = 0; i < NUM_CLASSES; ++i) m = fmaxf(m, sl[i]);
        float s = 0.f;
        for (int i = 0; i < NUM_CLASSES; ++i) s += expf(sl[i] - m);
        smax = m;
        ssum = s;
    }
    __syncthreads();

    if (t < NUM_CLASSES - 1) {
        const int j = t + 1;
        const float p = expf(sl[j] - smax) / ssum;
        const bool keep = p > SCORE_THRESH;

        const float bx0 = boxes[r * 4 + 0];
        const float by0 = boxes[r * 4 + 1];
        const float bx1 = boxes[r * 4 + 2];
        const float by1 = boxes[r * 4 + 3];
        const float w = bx1 - bx0 + 1.0f;
        const float hh = by1 - by0 + 1.0f;
        const float cx = bx0 + 0.5f * w;
        const float cy = by0 + 0.5f * hh;

        const float* reg = &sl[NUM_CLASSES + j * 4];
        const float dx = reg[0] * 0.1f;
        const float dy = reg[1] * 0.1f;
        const float dw = fminf(reg[2] * 0.2f, BBOX_XFORM_CLIP);
        const float dh = fminf(reg[3] * 0.2f, BBOX_XFORM_CLIP);

        const float pcx = dx * w + cx;
        const float pcy = dy * hh + cy;
        const float pw = expf(dw) * w;
        const float ph = expf(dh) * hh;

        float* orow = out + (size_t)r * ldo;
        orow[t] = keep ? p : 0.f;
        const int bo = (NUM_CLASSES - 1) + t * 4;
        orow[bo + 0] = keep ? (pcx - 0.5f * pw) : 0.f;
        orow[bo + 1] = keep ? (pcy - 0.5f * ph) : 0.f;
        orow[bo + 2] = keep ? (pcx + 0.5f * pw - 1.0f) : 0.f;
        orow[bo + 3] = keep ? (pcy + 0.5f * ph - 1.0f) : 0.f;
    }
}

// --------------------------- launch ---------------------------------------
extern "C" void kernel_launch(void* const* d_in, const int* in_sizes, int n_in,
                              void* d_out, int out_size) {
    const float* x      = (const float*)d_in[0];
    const float* boxes  = (const float*)d_in[1];
    const float* W6     = (const float*)d_in[2];
    const float* b6     = (const float*)d_in[3];
    const float* W7     = (const float*)d_in[4];
    const float* b7     = (const float*)d_in[5];
    const float* Wcls   = (const float*)d_in[6];
    const float* bcls   = (const float*)d_in[7];
    const float* Wbox   = (const float*)d_in[8];
    const float* bbox_b = (const float*)d_in[9];
    float* out = (float*)d_out;
    (void)n_in; (void)out_size;

    const int M  = in_sizes[1] / 4;       // 2000
    const int K1 = in_sizes[0] / M;       // 12544
    const int H  = in_sizes[3];           // 1024
    const int NC = in_sizes[7];           // 81
    const int OUTW = (NC - 1) * 5 + H;    // 1424

    __half *xh, *w6h, *w7h, *whh, *f6h, *f7h;
    float *part;
    cudaGetSymbolAddress((void**)&xh, g_xh);
    cudaGetSymbolAddress((void**)&w6h, g_w6h);
    cudaGetSymbolAddress((void**)&w7h, g_w7h);
    cudaGetSymbolAddress((void**)&whh, g_whh);
    cudaGetSymbolAddress((void**)&f6h, g_f6h);
    cudaGetSymbolAddress((void**)&f7h, g_f7h);
    cudaGetSymbolAddress((void**)&part, g_part);

    const int SMEM_BYTES = 3 * 32768;  // 96KB
    cudaFuncSetAttribute(hmma_gemm_f16,
                         cudaFuncAttributeMaxDynamicSharedMemorySize, SMEM_BYTES);

    // 1) mega prep: x -> fp16, all weights transposed fp16 (single grid)
    {
        const int nbW6 = (H / 32) * (K1 / 32);
        const int nbW7 = (H / 32) * (H / 32);
        const int nbWc = ((NC + 31) / 32) * (H / 32);
        const int nbWb = ((NC * 4 + 31) / 32) * (H / 32);
        const int nb = NBX + nbW6 + nbW7 + nbWc + nbWb;
        prep_kernel<<<nb, 256>>>(x, W6, W7, Wcls, Wbox,
                                 xh, w6h, w7h, whh, M, K1, H, NC);
    }

    const int MB = (M + 127) / 128;  // 16
    // 2) GEMM1 (split-K=2, Ksl=6272) + reduce -> f6 + fp16 copy
    hmma_gemm_f16<<<dim3(H / 128, MB, 2), 128, SMEM_BYTES>>>(
        M, H, K1, K1 / 2, xh, w6h, part);
    reduce_epilogue<<<(M * H / 2 + 255) / 256, 256>>>(
        M, H, part, b6, 1, out + (NC - 1) * 5, OUTW, f6h, H);
    // 3) GEMM2 (split-K=2, Ksl=512) + reduce -> f7 fp16
    hmma_gemm_f16<<<dim3(H / 128, MB, 2), 128, SMEM_BYTES>>>(
        M, H, H, H / 2, f6h, w7h, part);
    reduce_epilogue<<<(M * H / 2 + 255) / 256, 256>>>(
        M, H, part, b7, 1, nullptr, 0, f7h, H);
    // 4) head GEMM (split-K=2); reduce fused into postprocess
    hmma_gemm_f16<<<dim3(NHEAD / 128, MB, 2), 128, SMEM_BYTES>>>(
        M, NHEAD, H, H / 2, f7h, whh, part);
    // 5) postprocess (+head reduce + bias)
    postprocess_kernel<<<M, 128>>>(M, part, bcls, bbox_b, boxes, out, OUTW);
}